// round 3
// baseline (speedup 1.0000x reference)
#include <cuda_runtime.h>
#include <math.h>

#define N_NODES 100000
#define N_EDGES 3200000
#define CAP 96          // max in-degree slots per node (Poisson(32): P(overflow) ~ 1e-20)

// Scratch (static device globals; no allocation)
__device__ __align__(16) float g_bufA[(size_t)N_NODES * 12];
__device__ __align__(16) float g_bufB[(size_t)N_NODES * 12];
__device__ int    g_cursor[N_NODES];
__device__ float2 g_edges[(size_t)N_NODES * CAP];   // (edge_val, src as int bits), binned by dst

// ---------------------------------------------------------------------------
// Layer-1 dense MM: s1[100000,12] = x[100000,512] @ W1[512,12]
// warp-per-row, float4 x loads, W1 staged in shared (pad 13).
// ---------------------------------------------------------------------------
__global__ void mm1_kernel(const float* __restrict__ x,
                           const float* __restrict__ W,
                           float* __restrict__ out) {
    __shared__ float sW[512 * 13];
    for (int i = threadIdx.x; i < 512 * 12; i += blockDim.x) {
        int k = i / 12, j = i % 12;
        sW[k * 13 + j] = W[i];
    }
    __syncthreads();

    int warp = (blockIdx.x * blockDim.x + threadIdx.x) >> 5;
    int lane = threadIdx.x & 31;
    if (warp >= N_NODES) return;

    const float4* xr = reinterpret_cast<const float4*>(x + (size_t)warp * 512);
    float acc[12];
#pragma unroll
    for (int j = 0; j < 12; j++) acc[j] = 0.f;

#pragma unroll
    for (int it = 0; it < 4; it++) {
        int k4 = it * 32 + lane;
        float4 xv = xr[k4];
        int k = k4 * 4;
#pragma unroll
        for (int j = 0; j < 12; j++) {
            acc[j] = fmaf(xv.x, sW[(k + 0) * 13 + j], acc[j]);
            acc[j] = fmaf(xv.y, sW[(k + 1) * 13 + j], acc[j]);
            acc[j] = fmaf(xv.z, sW[(k + 2) * 13 + j], acc[j]);
            acc[j] = fmaf(xv.w, sW[(k + 3) * 13 + j], acc[j]);
        }
    }
#pragma unroll
    for (int j = 0; j < 12; j++) {
#pragma unroll
        for (int o = 16; o > 0; o >>= 1)
            acc[j] += __shfl_down_sync(0xffffffffu, acc[j], o);
    }
    if (lane == 0) {
        float* o = out + (size_t)warp * 12;
#pragma unroll
        for (int j = 0; j < 12; j++) o[j] = acc[j];
    }
}

// ---------------------------------------------------------------------------
// Bin edges by destination: g_edges[dst*CAP + pos] = (val, src)
// ---------------------------------------------------------------------------
__global__ void fill_bins_kernel(const float* __restrict__ ev,
                                 const int* __restrict__ src,
                                 const int* __restrict__ dst) {
    int e = blockIdx.x * blockDim.x + threadIdx.x;
    if (e >= N_EDGES) return;
    int d = dst[e];
    int pos = atomicAdd(&g_cursor[d], 1);
    if (pos < CAP)
        g_edges[(size_t)d * CAP + pos] = make_float2(ev[e], __int_as_float(src[e]));
}

// ---------------------------------------------------------------------------
// Fused gather + bias + activation + next-layer GEMM. Warp per node.
//   agg[n] = sum_{e in bin(n)} val_e * s[src_e, 0:DIN]
//   h = ACT(agg + bprev)
//   out[n, 0:DOUT] = h @ W          (ACT==3: final, out[n,0:DIN] = agg + bprev)
// ACT: 0=identity, 1=relu, 2=tanhshrink, 3=final(no W)
// ---------------------------------------------------------------------------
template <int DIN, int SIN, int DOUT, int SOUT, int ACT>
__global__ void gather_mm_kernel(const float* __restrict__ s,
                                 const float* __restrict__ W,
                                 const float* __restrict__ bprev,
                                 float* __restrict__ out) {
    __shared__ float sW[DIN * DOUT];
    __shared__ float sb[DIN];
    if (ACT != 3) {
        for (int i = threadIdx.x; i < DIN * DOUT; i += blockDim.x) sW[i] = W[i];
    }
    if (threadIdx.x < DIN) sb[threadIdx.x] = bprev[threadIdx.x];
    __syncthreads();

    int node = (blockIdx.x * blockDim.x + threadIdx.x) >> 5;
    int lane = threadIdx.x & 31;
    if (node >= N_NODES) return;

    int deg = g_cursor[node];
    deg = deg < CAP ? deg : CAP;

    float acc[DIN];
#pragma unroll
    for (int k = 0; k < DIN; k++) acc[k] = 0.f;

    const float2* elist = &g_edges[(size_t)node * CAP];
    constexpr int NC = (DIN + 3) / 4;   // float4 chunks covering DIN (SIN >= 4*NC)

    for (int i = lane; i < deg; i += 32) {
        float2 ed = elist[i];
        float v = ed.x;
        int srcn = __float_as_int(ed.y);
        const float4* row = reinterpret_cast<const float4*>(s + (size_t)srcn * SIN);
#pragma unroll
        for (int c = 0; c < NC; c++) {
            float4 t = row[c];
            if (4 * c + 0 < DIN) acc[4 * c + 0] = fmaf(v, t.x, acc[4 * c + 0]);
            if (4 * c + 1 < DIN) acc[4 * c + 1] = fmaf(v, t.y, acc[4 * c + 1]);
            if (4 * c + 2 < DIN) acc[4 * c + 2] = fmaf(v, t.z, acc[4 * c + 2]);
            if (4 * c + 3 < DIN) acc[4 * c + 3] = fmaf(v, t.w, acc[4 * c + 3]);
        }
    }

    // butterfly all-reduce across the warp
#pragma unroll
    for (int k = 0; k < DIN; k++) {
#pragma unroll
        for (int o = 16; o > 0; o >>= 1)
            acc[k] += __shfl_xor_sync(0xffffffffu, acc[k], o);
    }

    if (ACT == 3) {  // final layer: out = agg + b
        if (lane < DIN)
            out[(size_t)node * SOUT + lane] = acc[lane] + sb[lane];
        return;
    }

    if (lane < DOUT) {
        float h[DIN];
#pragma unroll
        for (int k = 0; k < DIN; k++) {
            float v = acc[k] + sb[k];
            if (ACT == 1) v = fmaxf(v, 0.f);
            else if (ACT == 2) v = v - tanhf(v);
            h[k] = v;
        }
        float a = 0.f;
#pragma unroll
        for (int k = 0; k < DIN; k++) a = fmaf(h[k], sW[k * DOUT + lane], a);
        out[(size_t)node * SOUT + lane] = a;
    }
}

// ---------------------------------------------------------------------------
// Launch
// ---------------------------------------------------------------------------
extern "C" void kernel_launch(void* const* d_in, const int* in_sizes, int n_in,
                              void* d_out, int out_size) {
    const float* x = nullptr;
    const float* ev = nullptr;
    const int* esrc = nullptr;
    const int* edst = nullptr;
    const float* W[6] = {0};
    const float* b[6] = {0};
    const int wsz[6] = {512 * 12, 12 * 10, 10 * 8, 8 * 6, 6 * 4, 4 * 7};
    const int bsz[6] = {12, 10, 8, 6, 4, 7};

    int edgeSeen = 0;
    for (int i = 0; i < n_in; i++) {
        int sz = in_sizes[i];
        if (sz == N_NODES * 512) {
            x = (const float*)d_in[i];
        } else if (sz == N_EDGES) {
            if (edgeSeen == 0) ev = (const float*)d_in[i];
            else if (edgeSeen == 1) esrc = (const int*)d_in[i];
            else edst = (const int*)d_in[i];
            edgeSeen++;
        } else {
            for (int j = 0; j < 6; j++) {
                if (sz == wsz[j]) W[j] = (const float*)d_in[i];
                else if (sz == bsz[j]) b[j] = (const float*)d_in[i];
            }
        }
    }

    float* bufA = nullptr;
    float* bufB = nullptr;
    int* cursor = nullptr;
    cudaGetSymbolAddress((void**)&bufA, g_bufA);
    cudaGetSymbolAddress((void**)&bufB, g_bufB);
    cudaGetSymbolAddress((void**)&cursor, g_cursor);
    float* out = (float*)d_out;

    const int TB = 256;
    auto blocks = [](long long n, int tb) { return (int)((n + tb - 1) / tb); };
    const int WB = blocks((long long)N_NODES * 32, TB);  // warp-per-node grids

    // Build dst bins (once per launch)
    cudaMemsetAsync(cursor, 0, (size_t)N_NODES * sizeof(int));
    fill_bins_kernel<<<blocks(N_EDGES, TB), TB>>>(ev, esrc, edst);

    // s1 = x @ W1   (width 12, stride 12)
    mm1_kernel<<<WB, TB>>>(x, W[0], bufA);

    // pass1: h1 = agg(s1)+b1 ; s2 = h1@W2        (10 wide, stride 12)
    gather_mm_kernel<12, 12, 10, 12, 0><<<WB, TB>>>(bufA, W[1], b[0], bufB);
    // pass2: h2 = relu(agg(s2)+b2) ; s3 = h2@W3  (8 wide, stride 8)
    gather_mm_kernel<10, 12, 8, 8, 1><<<WB, TB>>>(bufB, W[2], b[1], bufA);
    // pass3: h3 = ts(agg(s3)+b3) ; s4 = h3@W4    (6 wide, stride 8)
    gather_mm_kernel<8, 8, 6, 8, 2><<<WB, TB>>>(bufA, W[3], b[2], bufB);
    // pass4: h4 = ts(agg(s4)+b4) ; s5 = h4@W5    (4 wide, stride 4)
    gather_mm_kernel<6, 8, 4, 4, 2><<<WB, TB>>>(bufB, W[4], b[3], bufA);
    // pass5: h5 = agg(s5)+b5 ; s6 = h5@W6        (7 wide, stride 8)
    gather_mm_kernel<4, 4, 7, 8, 0><<<WB, TB>>>(bufA, W[5], b[4], bufB);
    // pass6 (final): out = agg(s6) + b6          (7 wide, stride 7, into d_out)
    gather_mm_kernel<7, 8, 7, 7, 3><<<WB, TB>>>(bufB, W[5], b[5], out);

    (void)out_size;
}

// round 4
// speedup vs baseline: 1.1514x; 1.1514x over previous
#include <cuda_runtime.h>
#include <math.h>

#define N_NODES 100000
#define N_EDGES 3200000
#define CAP 96          // max in-degree slots (Poisson(32): P(deg>96) ~ 1e-20)
#define STRIDE 16       // feature-row stride in floats (64B, line-aligned)

// Scratch (static device globals; no allocation)
__device__ __align__(128) float g_bufA[(size_t)N_NODES * STRIDE];
__device__ __align__(128) float g_bufB[(size_t)N_NODES * STRIDE];
__device__ int    g_cursor[N_NODES];
__device__ __align__(128) float2 g_edges[(size_t)N_NODES * CAP]; // (val, src-bits) binned by dst

// ---------------------------------------------------------------------------
// Layer-1 dense MM: s1[100000,12] = x[100000,512] @ W1[512,12]  (stride 16 out)
// ---------------------------------------------------------------------------
__global__ void mm1_kernel(const float* __restrict__ x,
                           const float* __restrict__ W,
                           float* __restrict__ out) {
    __shared__ float sW[512 * 13];
    for (int i = threadIdx.x; i < 512 * 12; i += blockDim.x) {
        int k = i / 12, j = i % 12;
        sW[k * 13 + j] = W[i];
    }
    __syncthreads();

    int warp = (blockIdx.x * blockDim.x + threadIdx.x) >> 5;
    int lane = threadIdx.x & 31;
    if (warp >= N_NODES) return;

    const float4* xr = reinterpret_cast<const float4*>(x + (size_t)warp * 512);
    float acc[12];
#pragma unroll
    for (int j = 0; j < 12; j++) acc[j] = 0.f;

#pragma unroll
    for (int it = 0; it < 4; it++) {
        int k4 = it * 32 + lane;
        float4 xv = xr[k4];
        int k = k4 * 4;
#pragma unroll
        for (int j = 0; j < 12; j++) {
            acc[j] = fmaf(xv.x, sW[(k + 0) * 13 + j], acc[j]);
            acc[j] = fmaf(xv.y, sW[(k + 1) * 13 + j], acc[j]);
            acc[j] = fmaf(xv.z, sW[(k + 2) * 13 + j], acc[j]);
            acc[j] = fmaf(xv.w, sW[(k + 3) * 13 + j], acc[j]);
        }
    }
#pragma unroll
    for (int j = 0; j < 12; j++) {
#pragma unroll
        for (int o = 16; o > 0; o >>= 1)
            acc[j] += __shfl_down_sync(0xffffffffu, acc[j], o);
    }
    if (lane == 0) {
        float* o = out + (size_t)warp * STRIDE;
#pragma unroll
        for (int j = 0; j < 12; j++) o[j] = acc[j];
    }
}

// ---------------------------------------------------------------------------
// Bin edges by destination: g_edges[dst*CAP + pos] = (val, src)
// ---------------------------------------------------------------------------
__global__ void fill_bins_kernel(const float* __restrict__ ev,
                                 const int* __restrict__ src,
                                 const int* __restrict__ dst) {
    int e = blockIdx.x * blockDim.x + threadIdx.x;
    if (e >= N_EDGES) return;
    int d = dst[e];
    int pos = atomicAdd(&g_cursor[d], 1);
    if (pos < CAP)
        g_edges[(size_t)d * CAP + pos] = make_float2(ev[e], __int_as_float(src[e]));
}

// ---------------------------------------------------------------------------
// Fused gather + bias + activation + next GEMM. Warp per node; feature-per-lane.
// Lane = (group g, feature j), group size DPAD, G = 32/DPAD groups.
// Group g streams edges e = g, g+G, ... ; the DPAD lanes of a group load
// s[src, 0:DPAD] COALESCED (row fits one 128B line thanks to STRIDE=16).
// Cross-group reduce = log2(G) shuffles. ACT: 0=id, 1=relu, 2=tanhshrink, 3=final
// ---------------------------------------------------------------------------
template <int DIN, int DPAD, int DOUT, int ACT, int SOUT>
__global__ void gather_mm_kernel(const float* __restrict__ s,
                                 const float* __restrict__ W,
                                 const float* __restrict__ bprev,
                                 float* __restrict__ out) {
    constexpr int G = 32 / DPAD;
    __shared__ float sW[(ACT == 3) ? 1 : (DIN * DOUT + 1)];
    __shared__ float sb[DIN];
    __shared__ float sh[8][DPAD];   // per-warp h vector (blockDim=256 -> 8 warps)

    if (ACT != 3)
        for (int i = threadIdx.x; i < DIN * DOUT; i += blockDim.x) sW[i] = W[i];
    if (threadIdx.x < DIN) sb[threadIdx.x] = bprev[threadIdx.x];
    __syncthreads();

    int warpid = threadIdx.x >> 5;
    int node = (blockIdx.x * blockDim.x + threadIdx.x) >> 5;
    int lane = threadIdx.x & 31;
    if (node >= N_NODES) return;

    int g = lane / DPAD;     // group id
    int j = lane % DPAD;     // feature id

    int deg = g_cursor[node];
    deg = deg < CAP ? deg : CAP;

    const float2* elist = &g_edges[(size_t)node * CAP];

    float acc0 = 0.f, acc1 = 0.f;
    int e = g;
    // 2-way unrolled for MLP across the dependent elist -> s[src] chains
    for (; e + G < deg; e += 2 * G) {
        float2 ed0 = elist[e];
        float2 ed1 = elist[e + G];
        int s0 = __float_as_int(ed0.y);
        int s1 = __float_as_int(ed1.y);
        acc0 = fmaf(ed0.x, __ldg(s + (size_t)s0 * STRIDE + j), acc0);
        acc1 = fmaf(ed1.x, __ldg(s + (size_t)s1 * STRIDE + j), acc1);
    }
    if (e < deg) {
        float2 ed = elist[e];
        int s0 = __float_as_int(ed.y);
        acc0 = fmaf(ed.x, __ldg(s + (size_t)s0 * STRIDE + j), acc0);
    }
    float acc = acc0 + acc1;

    // reduce across the G groups (lane j of every group holds partial of feature j)
#pragma unroll
    for (int o = DPAD; o < 32; o <<= 1)
        acc += __shfl_xor_sync(0xffffffffu, acc, o);

    if (ACT == 3) {  // final: out[node, j] = agg + b
        if (g == 0 && j < DIN)
            out[(size_t)node * SOUT + j] = acc + sb[j];
        return;
    }

    // bias + activation on feature j, stash h in per-warp smem
    if (g == 0) {
        float h = 0.f;
        if (j < DIN) {
            h = acc + sb[j];
            if (ACT == 1) h = fmaxf(h, 0.f);
            else if (ACT == 2) h = h - tanhf(h);
        }
        sh[warpid][j] = h;
    }
    __syncwarp();

    if (lane < DOUT) {
        float a = 0.f;
#pragma unroll
        for (int k = 0; k < DIN; k++)
            a = fmaf(sh[warpid][k], sW[k * DOUT + lane], a);
        out[(size_t)node * SOUT + lane] = a;
    }
}

// ---------------------------------------------------------------------------
// Launch
// ---------------------------------------------------------------------------
extern "C" void kernel_launch(void* const* d_in, const int* in_sizes, int n_in,
                              void* d_out, int out_size) {
    const float* x = nullptr;
    const float* ev = nullptr;
    const int* esrc = nullptr;
    const int* edst = nullptr;
    const float* W[6] = {0};
    const float* b[6] = {0};
    const int wsz[6] = {512 * 12, 12 * 10, 10 * 8, 8 * 6, 6 * 4, 4 * 7};
    const int bsz[6] = {12, 10, 8, 6, 4, 7};

    int edgeSeen = 0;
    for (int i = 0; i < n_in; i++) {
        int sz = in_sizes[i];
        if (sz == N_NODES * 512) {
            x = (const float*)d_in[i];
        } else if (sz == N_EDGES) {
            if (edgeSeen == 0) ev = (const float*)d_in[i];
            else if (edgeSeen == 1) esrc = (const int*)d_in[i];
            else edst = (const int*)d_in[i];
            edgeSeen++;
        } else {
            for (int j = 0; j < 6; j++) {
                if (sz == wsz[j]) W[j] = (const float*)d_in[i];
                else if (sz == bsz[j]) b[j] = (const float*)d_in[i];
            }
        }
    }

    float* bufA = nullptr;
    float* bufB = nullptr;
    int* cursor = nullptr;
    cudaGetSymbolAddress((void**)&bufA, g_bufA);
    cudaGetSymbolAddress((void**)&bufB, g_bufB);
    cudaGetSymbolAddress((void**)&cursor, g_cursor);
    float* out = (float*)d_out;

    const int TB = 256;
    auto blocks = [](long long n, int tb) { return (int)((n + tb - 1) / tb); };
    const int WB = blocks((long long)N_NODES * 32, TB);  // warp-per-node grids

    // Build dst bins (once per launch)
    cudaMemsetAsync(cursor, 0, (size_t)N_NODES * sizeof(int));
    fill_bins_kernel<<<blocks(N_EDGES, TB), TB>>>(ev, esrc, edst);

    // s1 = x @ W1  (12 wide, stride 16)
    mm1_kernel<<<WB, TB>>>(x, W[0], bufA);

    // pass1: (agg(s1)+b1) @ W2                  DIN=12 DPAD=16 DOUT=10
    gather_mm_kernel<12, 16, 10, 0, STRIDE><<<WB, TB>>>(bufA, W[1], b[0], bufB);
    // pass2: relu(agg(s2)+b2) @ W3              DIN=10 DPAD=16 DOUT=8
    gather_mm_kernel<10, 16, 8, 1, STRIDE><<<WB, TB>>>(bufB, W[2], b[1], bufA);
    // pass3: ts(agg(s3)+b3) @ W4                DIN=8  DPAD=8  DOUT=6
    gather_mm_kernel<8, 8, 6, 2, STRIDE><<<WB, TB>>>(bufA, W[3], b[2], bufB);
    // pass4: ts(agg(s4)+b4) @ W5                DIN=6  DPAD=8  DOUT=4
    gather_mm_kernel<6, 8, 4, 2, STRIDE><<<WB, TB>>>(bufB, W[4], b[3], bufA);
    // pass5: (agg(s5)+b5) @ W6                  DIN=4  DPAD=4  DOUT=7
    gather_mm_kernel<4, 4, 7, 0, STRIDE><<<WB, TB>>>(bufA, W[5], b[4], bufB);
    // pass6 (final): out = agg(s6) + b6         DIN=7  DPAD=8  -> packed stride 7
    gather_mm_kernel<7, 8, 7, 3, 7><<<WB, TB>>>(bufB, W[5], b[5], out);

    (void)out_size;
}